// round 14
// baseline (speedup 1.0000x reference)
#include <cuda_runtime.h>
#include <cstdint>
#include <cstddef>

// Problem shape (fixed by the reference setup_inputs)
#define BB 64
#define TT 2048
#define NN 32
#define DD 32           // tile ring stages (4 chunks of 8) = 128 KB
#define KCH 8           // steps per super-step / chunk
#define AR 32           // alpha ring slots
#define NTH 128
#define KNINF (-1e4f)
#define NEG_BIG (-3.402823466e38f)
#define LSEG 128
#define MAXSEG (TT / LSEG)   // 16

struct __align__(16) Smem {
    float tiles[DD][NN * NN];        // 128 KB; element (i,j) at i*128B + ((j^(i&16))*4)
    float aring[AR][NN];             // 4 KB alpha ring, slot = t & 31
    unsigned char back[TT][NN];      // 64 KB backpointers
    unsigned char M[MAXSEG][NN];     // composed segment maps
    int entry[MAXSEG];
    int misc[8];                     // [0..3] warp counts, [5] last_tag
};

__device__ __forceinline__ void cp16(unsigned dst, const void* src) {
    asm volatile("cp.async.cg.shared.global [%0], [%1], 16;" :: "r"(dst), "l"(src));
}
__device__ __forceinline__ void cp_commit() { asm volatile("cp.async.commit_group;"); }
template<int Nn> __device__ __forceinline__ void cp_wait() {
    asm volatile("cp.async.wait_group %0;" :: "n"(Nn));
}

__global__ void __launch_bounds__(NTH, 1)
viterbi_kernel(const float* __restrict__ lp, const int* __restrict__ mask,
               const int* __restrict__ startc, const int* __restrict__ endc,
               const int* __restrict__ transc, float* __restrict__ out)
{
    extern __shared__ __align__(16) char smraw[];
    Smem& sm = *reinterpret_cast<Smem*>(smraw);
    const int b    = blockIdx.x;
    const int tid  = threadIdx.x;
    const int w    = tid >> 5;
    const int lane = tid & 31;

    // ---- sequence length (mask is prefix-true) ----
    int cnt = 0;
    #pragma unroll
    for (int t = tid; t < TT; t += NTH) cnt += (mask[b * TT + t] != 0);
    #pragma unroll
    for (int o = 16; o; o >>= 1) cnt += __shfl_xor_sync(0xffffffffu, cnt, o);
    if (lane == 0) sm.misc[w] = cnt;
    __syncthreads();
    const int len  = sm.misc[0] + sm.misc[1] + sm.misc[2] + sm.misc[3];
    const int last = len - 1;

    const float* lpb = lp + (size_t)b * TT * NN * NN;
    const unsigned tilesBase = (unsigned)__cvta_generic_to_shared(&sm.tiles[0][0]);

    // ---- prologue: ALL threads cooperatively load chunks 0 and 1 (tiles 0..15) ----
    #pragma unroll 4
    for (int r = 0; r < 32; r++) {
        int g = tid + NTH * r;            // 0..4095 : 16 tiles x 256 16B-chunks
        int tg = g >> 8;                  // tile 0..15
        int within = g & 255;
        int ri = within >> 3, c = within & 7;
        unsigned dst = tilesBase + (unsigned)((tg & (DD - 1)) * 4096 + ri * 128
                       + ((c * 16) ^ ((ri & 16) ? 64 : 0)));
        const float* src = lpb + (size_t)tg * (NN * NN) + ri * NN + c * 4;
        cp16(dst, src);
    }
    cp_commit();
    cp_wait<0>();

    const int SSMAX = last / KCH + 2;     // uniform across warps

    if (w == 0) {
        // ================= alpha warp: lane = column j =================
        const int j = lane;
        float trv[NN];
        #pragma unroll
        for (int i = 0; i < NN; i++)
            trv[i] = transc[i * NN + j] ? 0.0f : KNINF;
        const float sp_j = startc[j] ? 0.0f : KNINF;
        const float ep_j = endc[j]   ? 0.0f : KNINF;

        for (int ss = 0; ss < SSMAX; ss++) {
            __syncthreads();              // chunk ss resident; ring slots free
            int tlo = ss * KCH;
            int thi = min(last, ss * KCH + KCH - 1);
            if (ss == 0) {
                // t = 0: alpha0[j] = max_i tile0[i][j] + sp (+ep if len==1)
                const float* tile = sm.tiles[0];
                float bv = NEG_BIG;
                #pragma unroll
                for (int i = 0; i < NN; i++)
                    bv = fmaxf(bv, tile[i * NN + (j ^ (i & 16))]);
                float e = (last == 0) ? ep_j : 0.0f;
                sm.aring[0][j] = (bv + sp_j) + e;
                __syncwarp();
                tlo = 1;
            }
            int thiN = min(thi, last - 1);       // normal steps (exclude end step)
            for (int t = tlo; t <= thiN; t++) {
                const float* tile = sm.tiles[t & (DD - 1)];
                const float* ap = sm.aring[(t - 1) & (AR - 1)];
                float a[NN];
                #pragma unroll
                for (int q = 0; q < 8; q++) {
                    float4 v = reinterpret_cast<const float4*>(ap)[q];
                    a[4*q] = v.x; a[4*q+1] = v.y; a[4*q+2] = v.z; a[4*q+3] = v.w;
                }
                float s[NN];
                #pragma unroll
                for (int i = 0; i < NN; i++)
                    s[i] = (tile[i * NN + (j ^ (i & 16))] + trv[i]) + a[i];
                #pragma unroll
                for (int off = 1; off < NN; off <<= 1)
                    #pragma unroll
                    for (int i = 0; i < NN; i += 2 * off)
                        s[i] = fmaxf(s[i], s[i + off]);
                sm.aring[t & (AR - 1)][j] = s[0];
                __syncwarp();
            }
            if (last >= 1 && last >= tlo && last <= thi) {
                // peeled end step: ((phi+tr)+ep)+alpha
                const int t = last;
                const float* tile = sm.tiles[t & (DD - 1)];
                const float* ap = sm.aring[(t - 1) & (AR - 1)];
                float a[NN];
                #pragma unroll
                for (int q = 0; q < 8; q++) {
                    float4 v = reinterpret_cast<const float4*>(ap)[q];
                    a[4*q] = v.x; a[4*q+1] = v.y; a[4*q+2] = v.z; a[4*q+3] = v.w;
                }
                float s[NN];
                #pragma unroll
                for (int i = 0; i < NN; i++)
                    s[i] = ((tile[i * NN + (j ^ (i & 16))] + trv[i]) + ep_j) + a[i];
                #pragma unroll
                for (int off = 1; off < NN; off <<= 1)
                    #pragma unroll
                    for (int i = 0; i < NN; i += 2 * off)
                        s[i] = fmaxf(s[i], s[i + off]);
                sm.aring[t & (AR - 1)][j] = s[0];
                __syncwarp();
            }
        }
    } else if (w <= 2) {
        // ========== backpointer warps: 16 columns each, 2 lanes/column ==========
        const int j    = (w - 1) * 16 + (lane & 15);
        const int half = lane >> 4;                 // i in [16*half, 16*half+15]
        const int coff = j ^ (half << 4);           // swizzled column (constant)
        float trv2[16];
        #pragma unroll
        for (int k = 0; k < 16; k++)
            trv2[k] = transc[(16 * half + k) * NN + j] ? 0.0f : KNINF;
        const float ep_j = endc[j] ? 0.0f : KNINF;

        for (int ss = 0; ss < SSMAX; ss++) {
            __syncthreads();
            if (ss >= 1) {
                int tlo = max(1, (ss - 1) * KCH);
                int thi = min(last, (ss - 1) * KCH + KCH - 1);
                for (int t = tlo; t <= thi; t++) {
                    const float* tile = sm.tiles[t & (DD - 1)];
                    const float* ap = &sm.aring[(t - 1) & (AR - 1)][half * 16];
                    float a2[16];
                    #pragma unroll
                    for (int q = 0; q < 4; q++) {
                        float4 v = reinterpret_cast<const float4*>(ap)[q];
                        a2[4*q] = v.x; a2[4*q+1] = v.y; a2[4*q+2] = v.z; a2[4*q+3] = v.w;
                    }
                    float sv[16];
                    if (t != last) {
                        #pragma unroll
                        for (int k = 0; k < 16; k++)
                            sv[k] = (tile[(16 * half + k) * NN + coff] + trv2[k]) + a2[k];
                    } else {
                        #pragma unroll
                        for (int k = 0; k < 16; k++)
                            sv[k] = ((tile[(16 * half + k) * NN + coff] + trv2[k]) + ep_j) + a2[k];
                    }
                    float m[16];
                    #pragma unroll
                    for (int k = 0; k < 16; k++) m[k] = sv[k];
                    #pragma unroll
                    for (int off = 1; off < 16; off <<= 1)
                        #pragma unroll
                        for (int k = 0; k < 16; k += 2 * off)
                            m[k] = fmaxf(m[k], m[k + off]);
                    const float lm = m[0];
                    int idx = 15;
                    #pragma unroll
                    for (int k = 14; k >= 0; k--)
                        if (sv[k] == lm) idx = k;             // first-max within half
                    int gi = half * 16 + idx;
                    float olm = __shfl_xor_sync(0xffffffffu, lm, 16);
                    int   ogi = __shfl_xor_sync(0xffffffffu, gi, 16);
                    // half0 decides: strictly-greater other half wins; ties -> half0 (smaller i)
                    int res = (olm > lm) ? ogi : gi;
                    if (half == 0) sm.back[t][j] = (unsigned char)res;
                }
            }
        }
    } else {
        // ================= prefetch warp: chunk ss+2 =================
        for (int ss = 0; ss < SSMAX; ss++) {
            __syncthreads();
            const int cn = ss + 2;
            #pragma unroll 4
            for (int r = 0; r < 64; r++) {
                int g = lane + 32 * r;            // 0..2047 : 8 tiles x 256 chunks
                int tl = g >> 8;
                int t_g = cn * KCH + tl;
                if (t_g <= last) {
                    int within = g & 255;
                    int ri = within >> 3, c = within & 7;
                    unsigned dst = tilesBase + (unsigned)((t_g & (DD - 1)) * 4096
                                   + ri * 128 + ((c * 16) ^ ((ri & 16) ? 64 : 0)));
                    const float* src = lpb + (size_t)t_g * (NN * NN) + ri * NN + c * 4;
                    cp16(dst, src);
                }
            }
            cp_commit();
            cp_wait<1>();    // chunk ss+1 resident before next barrier
        }
        cp_wait<0>();
    }

    __syncthreads();   // alpha[last], back[] all published

    // ---- final max / argmax over tags (first occurrence) ----
    if (w == 0) {
        float v  = sm.aring[last & (AR - 1)][lane];
        int  idx = lane;
        #pragma unroll
        for (int o = 16; o; o >>= 1) {
            float ov = __shfl_xor_sync(0xffffffffu, v, o);
            int   oi = __shfl_xor_sync(0xffffffffu, idx, o);
            if (ov > v || (ov == v && oi < idx)) { v = ov; idx = oi; }
        }
        if (lane == 0) { out[b] = v; sm.misc[5] = idx; }
    }
    __syncthreads();
    const int last_tag = sm.misc[5];

    float* tags = out + BB + (size_t)b * TT;
    for (int t = len + tid; t < TT; t += NTH) tags[t] = -1.0f;   // PADDING_INDEX

    if (last == 0) {
        if (tid == 0) tags[0] = (float)last_tag;
        return;
    }

    // ---- parallel backtrack: segment-composed pointer chase ----
    const int nseg = (last + LSEG - 1) / LSEG;
    for (int q = tid; q < nseg * NN; q += NTH) {
        const int s  = q >> 5;
        int y        = q & 31;
        const int lo = s * LSEG;
        const int hi = min((s + 1) * LSEG, last);
        for (int t = hi; t > lo; t--) y = sm.back[t][y];
        sm.M[s][q & 31] = (unsigned char)y;
    }
    __syncthreads();
    if (tid == 0) {
        int cur = last_tag;
        sm.entry[nseg - 1] = cur;
        for (int s = nseg - 1; s >= 1; s--) {
            cur = sm.M[s][cur];
            sm.entry[s - 1] = cur;
        }
        tags[0] = (float)sm.M[0][cur];
    }
    __syncthreads();
    if (tid < nseg) {
        const int s  = tid;
        const int lo = s * LSEG;
        const int hi = min((s + 1) * LSEG, last);
        int cur = sm.entry[s];
        for (int t = hi; t > lo; t--) {
            tags[t] = (float)cur;
            cur = sm.back[t][cur];
        }
    }
}

extern "C" void kernel_launch(void* const* d_in, const int* in_sizes, int n_in,
                              void* d_out, int out_size)
{
    const float* lp   = (const float*)d_in[0];
    const int* mask   = (const int*)d_in[1];
    const int* startc = (const int*)d_in[2];
    const int* endc   = (const int*)d_in[3];
    const int* transc = (const int*)d_in[4];
    float* out = (float*)d_out;
    (void)in_sizes; (void)n_in; (void)out_size;

    const int smem_bytes = (int)sizeof(Smem);   // ~201 KB (< 227 KB limit)
    cudaFuncSetAttribute(viterbi_kernel,
                         cudaFuncAttributeMaxDynamicSharedMemorySize, smem_bytes);
    viterbi_kernel<<<BB, NTH, smem_bytes>>>(lp, mask, startc, endc, transc, out);
}